// round 6
// baseline (speedup 1.0000x reference)
#include <cuda_runtime.h>
#include <cstdint>

// Problem constants
#define NB 32
#define H 640
#define W 640
#define HW (H*W)            // 409600
#define BOT 448             // int(640*0.7): region = rows [448, 640)
#define RH 192              // region rows
#define BROWS 32            // owned rows per band (6 bands)
#define GHALO 5
#define TR (BROWS + 2*GHALO)   // 42 tile rows
#define GW4 84              // gray tile width in u32 (336 bytes)
#define MW 12               // mask words per row (384-bit window)
#define THREADS 256
#define BLOCKS_PER_SM 6
#define TOTAL_BLOCKS 888    // 148 SMs * 6 resident blocks = one full wave
#define STRIPS 384          // 32 img * 6 bands * 2 halves
#define CHUNK_F4 1024
#define CHUNKS_PER_IMG 70   // 71680/1024
#define N_CHUNKS (NB*CHUNKS_PER_IMG)   // 2240
#define PLAIN_RANKS 504     // 888 - 384
#define IMG_F4_STRIDE (HW/4)

__device__ double g_part[TOTAL_BLOCKS][4];
__device__ unsigned int g_done;   // static zero-init; reset by last block each launch

__device__ __forceinline__ float bce_f(float l, float t) {
    return fmaxf(l, 0.f) - l * t + __logf(1.f + __expf(-fabsf(l)));
}

__device__ __forceinline__ uint32_t vrow_of(int g) {
    return ((unsigned)g < (unsigned)RH) ? 0xFFFFFFFFu : 0u;
}

__device__ __forceinline__ uint32_t fetch_w(const uint32_t (*buf)[MW], int rr, int w,
                                            uint32_t v, bool erode) {
    if ((unsigned)w >= (unsigned)MW) return 0u;
    uint32_t x = buf[rr][w];
    return erode ? (~x & v) : x;
}

// 3x3 morphology pass, bit-packed. erode == ~dilate(~m & valid) & valid
// (reduce_window SAME identity semantics at region borders / image cols).
__device__ __forceinline__ void morph_pass(const uint32_t (*in)[MW], uint32_t (*out)[MW],
                                           bool erode, int g0, uint32_t vm0, uint32_t vm11,
                                           int tid) {
    for (int idx = tid; idx < 40 * MW; idx += THREADS) {   // 2 iters
        int r = 1 + idx / MW;
        int w = idx - (r - 1) * MW;
        uint32_t vcol = (w == 0) ? vm0 : (w == MW - 1) ? vm11 : 0xFFFFFFFFu;
        uint32_t acc = 0;
        #pragma unroll
        for (int dr = -1; dr <= 1; dr++) {
            int rr = r + dr;                       // always within tile rows 0..41
            uint32_t v  = vrow_of(g0 + rr) & vcol;
            uint32_t vl = vrow_of(g0 + rr) & ((w - 1 == 0) ? vm0 : 0xFFFFFFFFu);
            uint32_t vr = vrow_of(g0 + rr) & ((w + 1 == MW - 1) ? vm11 : 0xFFFFFFFFu);
            uint32_t x  = fetch_w(in, rr, w,     v,  erode);
            uint32_t xl = fetch_w(in, rr, w - 1, vl, erode);
            uint32_t xr = fetch_w(in, rr, w + 1, vr, erode);
            acc |= x | (x << 1) | (x >> 1) | (xl >> 31) | (xr << 31);
        }
        if (erode) acc = ~acc;
        out[r][w] = acc & vrow_of(g0 + r) & vcol;
    }
    __syncthreads();
}

__device__ __forceinline__ void plain_chunk(int c, int tid,
                                            const float4* p4, const float4* g4,
                                            const float4* m4,
                                            float& sm, float& sbm) {
    int n    = c / CHUNKS_PER_IMG;
    int coff = (c - n * CHUNKS_PER_IMG) * CHUNK_F4;
    int base = n * IMG_F4_STRIDE + coff;
    #pragma unroll
    for (int u = 0; u < CHUNK_F4 / THREADS; u++) {    // 4
        int e = base + u * THREADS + tid;
        float4 mk = m4[e];
        float4 l  = p4[e];
        float4 tg = g4[e];
        sm  += mk.x + mk.y + mk.z + mk.w;
        sbm += bce_f(l.x, tg.x) * mk.x + bce_f(l.y, tg.y) * mk.y
             + bce_f(l.z, tg.z) * mk.z + bce_f(l.w, tg.w) * mk.w;
    }
}

__global__ __launch_bounds__(THREADS, BLOCKS_PER_SM)
void loss_kernel(const float* __restrict__ pred, const float* __restrict__ gt,
                 const float* __restrict__ mask, const float* __restrict__ img,
                 float* __restrict__ out)
{
    __shared__ uint32_t s_gray[TR][GW4];     // 14112 B
    __shared__ uint32_t s_mA[TR][MW];        // 2016 B
    __shared__ uint32_t s_mB[TR][MW];        // 2016 B
    __shared__ float    s_red[8][4];
    __shared__ double   s_fin[8][4];
    __shared__ bool     s_last;

    const int tid = threadIdx.x;
    const int bx  = blockIdx.x;
    const float4* p4 = (const float4*)pred;
    const float4* g4 = (const float4*)gt;
    const float4* m4 = (const float4*)mask;

    float sm = 0.f, sbm = 0.f, sc = 0.f, sbc = 0.f;

    const bool is_strip = (bx < 2 * STRIPS) && ((bx & 1) == 0);

    if (is_strip) {
        // ---------------- subtitle half-band block ----------------
        const int hs    = bx >> 1;                    // 0..383
        const int bandg = hs >> 1;
        const int h     = hs & 1;                     // column half
        const int n     = bandg / 6;
        const int band  = bandg - n * 6;
        const int g0    = band * BROWS - GHALO;       // region row of tile row 0
        const int gb4   = h * 80 - 2;                 // gray base col/4 (gbase = h*320-8)
        const float* ib = img + (size_t)n * 3 * HW;

        // Gray tile load (coalesced float4): 42 x 84 = 3528 items.
        for (int idx = tid; idx < TR * GW4; idx += THREADS) {
            int r  = idx / GW4;
            int t4 = idx - r * GW4;
            int g  = g0 + r;
            int c4 = gb4 + t4;
            uint32_t packed = 0u;
            if ((unsigned)g < (unsigned)RH && (unsigned)c4 < (unsigned)(W/4)) {
                int base = (BOT + g) * (W/4) + c4;
                float4 bb = ((const float4*)ib)[base];
                float4 gg = ((const float4*)ib)[base + HW/4];
                float4 rr = ((const float4*)ib)[base + 2*(HW/4)];
                #pragma unroll
                for (int i = 0; i < 4; i++) {
                    float b   = (i==0)?bb.x:(i==1)?bb.y:(i==2)?bb.z:bb.w;
                    float gch = (i==0)?gg.x:(i==1)?gg.y:(i==2)?gg.z:gg.w;
                    float rch = (i==0)?rr.x:(i==1)?rr.y:(i==2)?rr.z:rr.w;
                    b   = fminf(fmaxf(floorf(__fmul_rn(b  , 255.f)), 0.f), 255.f);
                    gch = fminf(fmaxf(floorf(__fmul_rn(gch, 255.f)), 0.f), 255.f);
                    rch = fminf(fmaxf(floorf(__fmul_rn(rch, 255.f)), 0.f), 255.f);
                    float gf = __fadd_rn(__fadd_rn(__fmul_rn(0.114f, b),
                                                   __fmul_rn(0.587f, gch)),
                                         __fmul_rn(0.299f, rch));
                    int g8 = (int)rintf(gf);   // round-half-even = jnp.round
                    packed |= ((uint32_t)g8 & 0xFFu) << (8 * i);
                }
            }
            s_gray[r][t4] = packed;
        }
        if (tid < MW) {                 // boundary rows for morph buffers
            s_mA[0][tid] = 0u; s_mA[TR-1][tid] = 0u;
            s_mB[0][tid] = 0u; s_mB[TR-1][tid] = 0u;
        }
        __syncthreads();

        // m0 = bright & contrast, words m=0..11 (global cols h*320-32+32m+bit).
        const uint8_t* G = (const uint8_t*)s_gray;
        for (int idx = tid; idx < 40 * MW; idx += THREADS) {   // 2 iters
            int r = 1 + idx / MW;
            int m = idx - (r - 1) * MW;
            int g = g0 + r;
            uint32_t word = 0u;
            if ((unsigned)g < (unsigned)RH) {
                // bright mask via SIMD byte compare over the 8 gray u32s
                uint32_t bright = 0u;
                #pragma unroll
                for (int j = 0; j < 8; j++) {
                    int t4 = 8 * m - 6 + j;
                    if ((unsigned)t4 < (unsigned)GW4) {
                        uint32_t one = __vsetgeu4(s_gray[r][t4], 0xCDCDCDCDu); // >=205
                        bright |= (((one & 0x01010101u) * 0x01020408u) >> 24 & 0xFu) << (4 * j);
                    }
                }
                int ru = (g == 0)      ? r + 1 : r - 1;
                int rd = (g == RH - 1) ? r - 1 : r + 1;
                const uint8_t* row = G + r * (GW4 * 4);
                const uint8_t* upr = G + ru * (GW4 * 4);
                const uint8_t* dnr = G + rd * (GW4 * 4);
                while (bright) {
                    int bit = __ffs(bright) - 1; bright &= bright - 1;
                    int t  = 32 * m + bit - 24;
                    int gc = h * 320 + 32 * m + bit - 32;
                    if ((unsigned)gc >= (unsigned)W) continue;
                    int tl  = (gc == 0)     ? t + 1 : t - 1;
                    int tr_ = (gc == W - 1) ? t - 1 : t + 1;
                    if ((unsigned)tl >= 336u || (unsigned)tr_ >= 336u) continue;
                    int cc = row[t];
                    int lap = upr[t] + dnr[t] + row[tl] + row[tr_] - 4 * cc;
                    if (lap >= 77 || lap <= -77)
                        word |= (1u << bit);
                }
            }
            s_mA[r][m] = word;
        }
        __syncthreads();

        // vm for edge words: h=0 word0 = cols<0; h=1 word11 = cols>=640.
        const uint32_t vm0  = (h == 0) ? 0u : 0xFFFFFFFFu;
        const uint32_t vm11 = (h == 1) ? 0u : 0xFFFFFFFFu;

        morph_pass(s_mA, s_mB, false, g0, vm0, vm11, tid);  // dilate
        morph_pass(s_mB, s_mA, true,  g0, vm0, vm11, tid);  // erode  (close done)
        morph_pass(s_mA, s_mB, true,  g0, vm0, vm11, tid);  // erode
        morph_pass(s_mB, s_mA, false, g0, vm0, vm11, tid);  // dilate (open done)

        // Region sums over owned 32 rows x 320 cols.
        for (int idx = tid; idx < BROWS * 80; idx += THREADS) {   // 10 iters
            int r   = GHALO + idx / 80;
            int c4l = idx - (r - GHALO) * 80;
            int g   = g0 + r;
            int e   = n * HW + (BOT + g) * W + h * 320 + c4l * 4;
            float4 mk = *(const float4*)(mask + e);
            float4 l  = *(const float4*)(pred + e);
            float4 tg = *(const float4*)(gt   + e);
            float b0 = bce_f(l.x, tg.x);
            float b1 = bce_f(l.y, tg.y);
            float b2 = bce_f(l.z, tg.z);
            float b3 = bce_f(l.w, tg.w);
            sm  += mk.x + mk.y + mk.z + mk.w;
            sbm += b0 * mk.x + b1 * mk.y + b2 * mk.z + b3 * mk.w;

            uint32_t mword = s_mA[r][1 + (c4l >> 3)];   // owned word = 1 + col/32
            int sh = (c4l & 7) * 4;
            float f0 = (float)((mword >> (sh + 0)) & 1u);
            float f1 = (float)((mword >> (sh + 1)) & 1u);
            float f2 = (float)((mword >> (sh + 2)) & 1u);
            float f3 = (float)((mword >> (sh + 3)) & 1u);
            sc  += f0 * mk.x + f1 * mk.y + f2 * mk.z + f3 * mk.w;
            sbc += f0 * b0 * mk.x + f1 * b1 * mk.y + f2 * b2 * mk.z + f3 * b3 * mk.w;
        }
    } else {
        // ---------------- plain block ----------------
        // plain rank j in 0..503: odd blocks below 768 -> j = bx>>1;
        // blocks >= 768 -> j = 384 + (bx - 768).
        int j = (bx < 2 * STRIPS) ? (bx >> 1) : (STRIPS + (bx - 2 * STRIPS));
        // 2240 chunks over 504 ranks: first 224 ranks get 5, rest get 4.
        int start = (j < 224) ? j * 5 : 224 * 5 + (j - 224) * 4;
        int cnt   = (j < 224) ? 5 : 4;
        for (int q = 0; q < cnt; q++)
            plain_chunk(start + q, tid, p4, g4, m4, sm, sbm);
    }

    // ---------------- in-block reduction -> per-block slot ----------------
    #pragma unroll
    for (int o = 16; o; o >>= 1) {
        sm  += __shfl_down_sync(0xFFFFFFFFu, sm,  o);
        sbm += __shfl_down_sync(0xFFFFFFFFu, sbm, o);
        sc  += __shfl_down_sync(0xFFFFFFFFu, sc,  o);
        sbc += __shfl_down_sync(0xFFFFFFFFu, sbc, o);
    }
    int warp = tid >> 5, lane = tid & 31;
    if (lane == 0) {
        s_red[warp][0] = sm;  s_red[warp][1] = sbm;
        s_red[warp][2] = sc;  s_red[warp][3] = sbc;
    }
    __syncthreads();
    if (tid == 0) {
        double a0 = 0, a1 = 0, a2 = 0, a3 = 0;
        #pragma unroll
        for (int w = 0; w < 8; w++) {
            a0 += (double)s_red[w][0];
            a1 += (double)s_red[w][1];
            a2 += (double)s_red[w][2];
            a3 += (double)s_red[w][3];
        }
        g_part[bx][0] = a0;
        g_part[bx][1] = a1;
        g_part[bx][2] = a2;
        g_part[bx][3] = a3;
        __threadfence();
        unsigned prev = atomicAdd(&g_done, 1u);
        s_last = (prev == TOTAL_BLOCKS - 1);
    }
    __syncthreads();

    if (s_last) {
        __threadfence();
        double a0 = 0, a1 = 0, a2 = 0, a3 = 0;
        for (int b = tid; b < TOTAL_BLOCKS; b += THREADS) {
            a0 += g_part[b][0];
            a1 += g_part[b][1];
            a2 += g_part[b][2];
            a3 += g_part[b][3];
        }
        int w2 = tid >> 5, l2 = tid & 31;
        #pragma unroll
        for (int o = 16; o; o >>= 1) {
            a0 += __shfl_down_sync(0xFFFFFFFFu, a0, o);
            a1 += __shfl_down_sync(0xFFFFFFFFu, a1, o);
            a2 += __shfl_down_sync(0xFFFFFFFFu, a2, o);
            a3 += __shfl_down_sync(0xFFFFFFFFu, a3, o);
        }
        if (l2 == 0) {
            s_fin[w2][0] = a0; s_fin[w2][1] = a1;
            s_fin[w2][2] = a2; s_fin[w2][3] = a3;
        }
        __syncthreads();
        if (tid == 0) {
            double b0 = 0, b1 = 0, b2 = 0, b3 = 0;
            #pragma unroll
            for (int w = 0; w < 8; w++) {
                b0 += s_fin[w][0]; b1 += s_fin[w][1];
                b2 += s_fin[w][2]; b3 += s_fin[w][3];
            }
            double loss;
            if (b2 > 0.0) loss = b3 / fmax(b2, 1e-6);
            else          loss = b1 / fmax(b0, 1e-6);
            out[0] = (float)loss;
            g_done = 0;
            __threadfence();
        }
    }
}

extern "C" void kernel_launch(void* const* d_in, const int* in_sizes, int n_in,
                              void* d_out, int out_size) {
    const float* others[3];
    const float* img = nullptr;
    int k = 0;
    for (int i = 0; i < n_in; i++) {
        if (in_sizes[i] == NB * 3 * HW && img == nullptr) img = (const float*)d_in[i];
        else if (k < 3) others[k++] = (const float*)d_in[i];
    }
    const float* pred = others[0];
    const float* gt   = others[1];
    const float* mask = others[2];
    if (img == nullptr && n_in >= 4) img = (const float*)d_in[3];

    loss_kernel<<<TOTAL_BLOCKS, THREADS>>>(pred, gt, mask, img, (float*)d_out);
}